// round 12
// baseline (speedup 1.0000x reference)
#include <cuda_runtime.h>
#include <cuda_fp16.h>
#include <math.h>

// Problem constants (shapes fixed by the dataset)
#define HC   128      // HEADS * C
#define CD   64       // C
#define FIN  128      // Fin of layer 1
#define NMAX 50048
#define EMAX 800256
#define ETMAX (NMAX + EMAX)
#define SCAN_CHUNK 2048   // elements per scan block (256 thr x 8)
#define HSCALE 4096.0f    // fp16 storage scale (keeps layer-2 h out of subnormals)
#define HSCALE_INV (1.0f / 4096.0f)

// ---------------- scratch (device globals; no allocation) ----------------
__device__ __align__(16) __half g_hh[(size_t)NMAX * HC];    // GEMM output * HSCALE, fp16
__device__ __align__(16) float  g_tmp[(size_t)NMAX * HC];   // raw gather acc [N,2,64] fp32
__device__ __align__(8)  float  g_sdst[NMAX * 2];           // per-node dst-scores [N,H]
__device__ __align__(8)  float  g_ssrc[NMAX * 2];           // per-node src-scores [N,H]
__device__ float    g_sum[4];                   // per-layer per-head exp sums
// CSR: g_deg stores EXTRA in-degree (self-loop excluded); zero-init and
// reset-after-use by offsets_kernel -> replay-clean with no init pass.
__device__ __align__(16) int g_deg[NMAX];
__device__ __align__(16) int g_roff[NMAX + 8];
__device__ __align__(16) int g_cursor[NMAX];
__device__ int      g_csr[ETMAX];               // src per incoming edge (dst-sorted)
__device__ int      g_bsum[256];                // per-block degree sums

__device__ __forceinline__ unsigned f2tf32(float f) {
    unsigned r;
    asm("cvt.rna.tf32.f32 %0, %1;" : "=r"(r) : "f"(f));
    return r;
}

__device__ __forceinline__ void mma_tf32(
    float& c0, float& c1, float& c2, float& c3,
    unsigned a0, unsigned a1, unsigned a2, unsigned a3,
    unsigned b0, unsigned b1)
{
    asm volatile(
        "mma.sync.aligned.m16n8k8.row.col.f32.tf32.tf32.f32 "
        "{%0,%1,%2,%3}, {%4,%5,%6,%7}, {%8,%9}, {%0,%1,%2,%3};"
        : "+f"(c0), "+f"(c1), "+f"(c2), "+f"(c3)
        : "r"(a0), "r"(a1), "r"(a2), "r"(a3), "r"(b0), "r"(b1));
}

// per-block dtype detection: int64 edges (<2^31) have all-zero odd words.
__device__ __forceinline__ int block_detect_is32(const int* __restrict__ ei32) {
    __shared__ int sIs32;
    if (threadIdx.x == 0) {
        unsigned v = 0;
#pragma unroll
        for (int i = 0; i < 32; i++) v |= (unsigned)ei32[2 * i + 1];
        sIs32 = (v != 0u) ? 1 : 0;
    }
    __syncthreads();
    return sIs32;
}

__device__ __forceinline__ void load_edge(const int* __restrict__ ei32,
                                          int e, int E, int is32, int& s, int& d) {
    if (is32) { s = ei32[e];     d = ei32[E + e]; }
    else      { s = ei32[2 * e]; d = ei32[2 * (E + e)]; }
}

__device__ __forceinline__ float lrexp(float a) {
    a = (a >= 0.f) ? a : 0.2f * a;
    return __expf(a);
}

// ---------------- tf32 tensor-core GEMM + fused score epilogue --------------
// Blocks [0, nGemm): GEMM. Blocks >= nGemm: degree histogram (layer 1 only).
// fromTmp=1 (layer 2): loader reads g_tmp and applies layer-1 normalization
// (inv from g_sum[0,1]) + bias + relu on the fly.
#define TP 36   // smem pitch (32 k + 4 pad) -> conflict-free fragment loads

template <int K>
__global__ void __launch_bounds__(256) gemm_tc_kernel(
    const float* __restrict__ X0, int fromTmp, const float* __restrict__ bias1,
    const float* __restrict__ W, const float* __restrict__ att, int N,
    const int* __restrict__ ei32, int nHistE, int nGemm)
{
    // ---- histogram part (layer-1 launch only) ----
    if (blockIdx.x >= (unsigned)nGemm) {
        int hb = blockIdx.x - nGemm;
        int is32 = block_detect_is32(ei32);
        if (hb == 0 && threadIdx.x < 4) g_sum[threadIdx.x] = 0.f;
        int e = hb * 256 + threadIdx.x;
        if (e < nHistE) {
            int s, d;
            load_edge(ei32, e, nHistE, is32, s, d);
            atomicAdd(&g_deg[d], 1);
        }
        return;
    }

    __shared__ __align__(16) unsigned sX[128 * TP];
    __shared__ __align__(16) unsigned sW[128 * TP];
    __shared__ float sAtt[256];

    int t    = threadIdx.x;
    int wid  = t >> 5;
    int lane = t & 31;
    int gid  = lane >> 2;
    int tid  = lane & 3;
    int wm   = wid & 3;
    int wn   = wid >> 2;    // head
    int row0 = blockIdx.x * 128;
    int wrow = wm * 32;
    int wcol = wn * 64;

    if (t < 256) sAtt[t] = att[t];

    float inv0 = 0.f, inv1 = 0.f;
    if (fromTmp) {
        inv0 = 0.5f * HSCALE_INV / (g_sum[0] + 1e-10f);
        inv1 = 0.5f * HSCALE_INV / (g_sum[1] + 1e-10f);
    }

    float c[2][8][4];
#pragma unroll
    for (int mt = 0; mt < 2; mt++)
#pragma unroll
        for (int nt = 0; nt < 8; nt++)
#pragma unroll
            for (int i = 0; i < 4; i++) c[mt][nt][i] = 0.f;

    for (int kc = 0; kc < K; kc += 32) {
#pragma unroll
        for (int it = 0; it < 4; it++) {
            int idx = t + it * 256;
            int r = idx >> 3;
            int q = idx & 7;
            int k = q * 4;

            float4 v = make_float4(0.f, 0.f, 0.f, 0.f);
            int grow = row0 + r;
            if (grow < N) {
                if (fromTmp) {
                    // layer-1 output = relu(tmp0*inv0 + tmp1*inv1 + b1)
                    int qi = (kc + k) >> 2;   // float4 index in [0,16)
                    const float4* t4 = reinterpret_cast<const float4*>(g_tmp)
                                       + (size_t)grow * 32;
                    float4 t0 = t4[qi], t1 = t4[qi + 16];
                    float4 bb = reinterpret_cast<const float4*>(bias1)[qi];
                    v.x = fmaxf(fmaf(t0.x, inv0, fmaf(t1.x, inv1, bb.x)), 0.f);
                    v.y = fmaxf(fmaf(t0.y, inv0, fmaf(t1.y, inv1, bb.y)), 0.f);
                    v.z = fmaxf(fmaf(t0.z, inv0, fmaf(t1.z, inv1, bb.z)), 0.f);
                    v.w = fmaxf(fmaf(t0.w, inv0, fmaf(t1.w, inv1, bb.w)), 0.f);
                } else {
                    v = *reinterpret_cast<const float4*>(X0 + (size_t)grow * K + kc + k);
                }
            }
            uint4 tv = make_uint4(f2tf32(v.x), f2tf32(v.y), f2tf32(v.z), f2tf32(v.w));
            *reinterpret_cast<uint4*>(&sX[r * TP + k]) = tv;

            float4 w = *reinterpret_cast<const float4*>(W + (size_t)r * K + kc + k);
            uint4 tw = make_uint4(f2tf32(w.x), f2tf32(w.y), f2tf32(w.z), f2tf32(w.w));
            *reinterpret_cast<uint4*>(&sW[r * TP + k]) = tw;
        }
        __syncthreads();

#pragma unroll
        for (int ks = 0; ks < 4; ks++) {
            int k0 = ks * 8;
            unsigned a[2][4];
#pragma unroll
            for (int mt = 0; mt < 2; mt++) {
                int r = wrow + mt * 16 + gid;
                a[mt][0] = sX[r * TP + k0 + tid];
                a[mt][1] = sX[(r + 8) * TP + k0 + tid];
                a[mt][2] = sX[r * TP + k0 + tid + 4];
                a[mt][3] = sX[(r + 8) * TP + k0 + tid + 4];
            }
            unsigned b[8][2];
#pragma unroll
            for (int nt = 0; nt < 8; nt++) {
                int n = wcol + nt * 8 + gid;
                b[nt][0] = sW[n * TP + k0 + tid];
                b[nt][1] = sW[n * TP + k0 + tid + 4];
            }
#pragma unroll
            for (int mt = 0; mt < 2; mt++)
#pragma unroll
                for (int nt = 0; nt < 8; nt++)
                    mma_tf32(c[mt][nt][0], c[mt][nt][1], c[mt][nt][2], c[mt][nt][3],
                             a[mt][0], a[mt][1], a[mt][2], a[mt][3],
                             b[nt][0], b[nt][1]);
        }
        __syncthreads();
    }

    float dp[2][2] = {{0.f, 0.f}, {0.f, 0.f}};
    float sp[2][2] = {{0.f, 0.f}, {0.f, 0.f}};

#pragma unroll
    for (int mt = 0; mt < 2; mt++) {
        int rlo = row0 + wrow + mt * 16 + gid;
        int rhi = rlo + 8;
#pragma unroll
        for (int nt = 0; nt < 8; nt++) {
            int cw = nt * 8 + tid * 2;
            int gc = wcol + cw;
            float c0 = c[mt][nt][0], c1 = c[mt][nt][1];
            float c2 = c[mt][nt][2], c3 = c[mt][nt][3];
            if (rlo < N)
                *reinterpret_cast<__half2*>(g_hh + (size_t)rlo * HC + gc) =
                    __floats2half2_rn(c0 * HSCALE, c1 * HSCALE);
            if (rhi < N)
                *reinterpret_cast<__half2*>(g_hh + (size_t)rhi * HC + gc) =
                    __floats2half2_rn(c2 * HSCALE, c3 * HSCALE);

            float ad0 = sAtt[wn * 128 + cw],      ad1 = sAtt[wn * 128 + cw + 1];
            float as0 = sAtt[wn * 128 + 64 + cw], as1 = sAtt[wn * 128 + 64 + cw + 1];
            dp[mt][0] = fmaf(c0, ad0, fmaf(c1, ad1, dp[mt][0]));
            sp[mt][0] = fmaf(c0, as0, fmaf(c1, as1, sp[mt][0]));
            dp[mt][1] = fmaf(c2, ad0, fmaf(c3, ad1, dp[mt][1]));
            sp[mt][1] = fmaf(c2, as0, fmaf(c3, as1, sp[mt][1]));
        }
    }
#pragma unroll
    for (int mt = 0; mt < 2; mt++)
#pragma unroll
        for (int u = 0; u < 2; u++) {
#pragma unroll
            for (int o = 1; o <= 2; o <<= 1) {
                dp[mt][u] += __shfl_xor_sync(0xffffffffu, dp[mt][u], o);
                sp[mt][u] += __shfl_xor_sync(0xffffffffu, sp[mt][u], o);
            }
            if (tid == 0) {
                int row = row0 + wrow + mt * 16 + gid + u * 8;
                if (row < N) {
                    g_sdst[row * 2 + wn] = dp[mt][u];
                    g_ssrc[row * 2 + wn] = sp[mt][u];
                }
            }
        }
}

// ---------------- scan phase 1: per-block sums (vectorized, warp reduce) ----
__global__ void __launch_bounds__(256) partial_kernel(int N) {
    int b = blockIdx.x, t = threadIdx.x;
    int beg = b * SCAN_CHUNK + t * 8;
    int s = 0;
    if (beg + 8 <= N) {
        int4 a = *reinterpret_cast<const int4*>(g_deg + beg);
        int4 c = *reinterpret_cast<const int4*>(g_deg + beg + 4);
        s = a.x + a.y + a.z + a.w + c.x + c.y + c.z + c.w + 8;
    } else {
#pragma unroll
        for (int i = 0; i < 8; i++) {
            int idx = beg + i;
            if (idx < N) s += g_deg[idx] + 1;
        }
    }
    s = __reduce_add_sync(0xffffffffu, s);
    __shared__ int wsum[8];
    if ((t & 31) == 0) wsum[t >> 5] = s;
    __syncthreads();
    if (t == 0) {
        int tot = 0;
#pragma unroll
        for (int i = 0; i < 8; i++) tot += wsum[i];
        g_bsum[b] = tot;
    }
}

// ---------------- scan phase 2: offsets (warp-shuffle scan, vectorized) -----
__global__ void __launch_bounds__(256) offsets_kernel(int N, int nb) {
    __shared__ int sBase;
    __shared__ int wsum[8];
    int b = blockIdx.x, t = threadIdx.x;
    int lane = t & 31, w = t >> 5;

    if (t < 32) {
        int val = (t < nb) ? g_bsum[t] : 0;
        int base = __reduce_add_sync(0xffffffffu, (t < b) ? val : 0);
        if (t == 0) sBase = base;
        if (b == 0) {
            int total = __reduce_add_sync(0xffffffffu, val);
            if (t == 0) g_roff[N] = total;
        }
    }

    int beg = b * SCAN_CHUNK + t * 8;
    int v[8];
    int s;
    bool vec = (beg + 8 <= N);
    if (vec) {
        int4 a = *reinterpret_cast<const int4*>(g_deg + beg);
        int4 c = *reinterpret_cast<const int4*>(g_deg + beg + 4);
        v[0] = a.x + 1; v[1] = a.y + 1; v[2] = a.z + 1; v[3] = a.w + 1;
        v[4] = c.x + 1; v[5] = c.y + 1; v[6] = c.z + 1; v[7] = c.w + 1;
        int4 z = make_int4(0, 0, 0, 0);
        *reinterpret_cast<int4*>(g_deg + beg)     = z;
        *reinterpret_cast<int4*>(g_deg + beg + 4) = z;
    } else {
#pragma unroll
        for (int i = 0; i < 8; i++) {
            int idx = beg + i;
            v[i] = (idx < N) ? (g_deg[idx] + 1) : 0;
            if (idx < N) g_deg[idx] = 0;
        }
    }
    s = v[0] + v[1] + v[2] + v[3] + v[4] + v[5] + v[6] + v[7];

    int ps = s;
#pragma unroll
    for (int o = 1; o < 32; o <<= 1) {
        int x = __shfl_up_sync(0xffffffffu, ps, o);
        if (lane >= o) ps += x;
    }
    if (lane == 31) wsum[w] = ps;
    __syncthreads();
    int wbase = 0;
#pragma unroll
    for (int j = 0; j < 8; j++) wbase += (j < w) ? wsum[j] : 0;

    int excl = (ps - s) + wbase + sBase;
    int r[8];
#pragma unroll
    for (int i = 0; i < 8; i++) { r[i] = excl; excl += v[i]; }
    if (vec) {
        *reinterpret_cast<int4*>(g_roff + beg)       = make_int4(r[0], r[1], r[2], r[3]);
        *reinterpret_cast<int4*>(g_roff + beg + 4)   = make_int4(r[4], r[5], r[6], r[7]);
        *reinterpret_cast<int4*>(g_cursor + beg)     = make_int4(r[0], r[1], r[2], r[3]);
        *reinterpret_cast<int4*>(g_cursor + beg + 4) = make_int4(r[4], r[5], r[6], r[7]);
    } else {
#pragma unroll
        for (int i = 0; i < 8; i++) {
            int idx = beg + i;
            if (idx < N) { g_roff[idx] = r[i]; g_cursor[idx] = r[i]; }
        }
    }
}

// ---------------- scatter: pure CSR build, 4 edges/thread (MLP) --------------
__global__ void __launch_bounds__(256) scatter_kernel(
    const int* __restrict__ ei32, int E, int N)
{
    int is32 = block_detect_is32(ei32);
    int base = (blockIdx.x * blockDim.x + threadIdx.x) * 4;
    int ET = E + N;

    int s[4], d[4];
    bool ok[4];
#pragma unroll
    for (int i = 0; i < 4; i++) {
        int e = base + i;
        ok[i] = (e < ET);
        s[i] = 0; d[i] = 0;
        if (ok[i]) {
            if (e < E) load_edge(ei32, e, E, is32, s[i], d[i]);
            else       { s[i] = e - E; d[i] = e - E; }
        }
    }
    int pos[4];
#pragma unroll
    for (int i = 0; i < 4; i++)
        if (ok[i]) pos[i] = atomicAdd(&g_cursor[d[i]], 1);
#pragma unroll
    for (int i = 0; i < 4; i++)
        if (ok[i]) g_csr[pos[i]] = s[i];
}

// ---------------- gather: raw (unnormalized) acc + fused denominator sums ----
__global__ void __launch_bounds__(256) gather_kernel(int N, int layer)
{
    int wid  = (blockIdx.x * blockDim.x + threadIdx.x) >> 5;
    int lane = threadIdx.x & 31;
    int wIdx = threadIdx.x >> 5;
    bool active = (wid < N);
    int d = active ? wid : 0;

    int g   = lane & 15;
    int sub = lane >> 4;
    bool isH1 = (g >= 8);

    const uint4* hv = reinterpret_cast<const uint4*>(g_hh);
    float acc[8];
#pragma unroll
    for (int i = 0; i < 8; i++) acc[i] = 0.f;
    float ws0 = 0.f, ws1 = 0.f;

    if (active) {
        int beg = g_roff[d];
        int end = g_roff[d + 1];
        float2 scd = *reinterpret_cast<const float2*>(g_sdst + d * 2);

        for (int base = beg; base < end; base += 32) {
            int idx = base + lane;
            int   s   = 0;
            float aw0 = 0.f, aw1 = 0.f;
            if (idx < end) {
                s = g_csr[idx];
                float2 scs = *reinterpret_cast<const float2*>(g_ssrc + s * 2);
                aw0 = lrexp(scd.x + scs.x);
                aw1 = lrexp(scd.y + scs.y);
                ws0 += aw0;
                ws1 += aw1;
            }
            int cnt = min(32, end - base);
#pragma unroll 4
            for (int j = 0; j < cnt; j += 2) {
                int jj = j + sub;
                int   sj = __shfl_sync(0xffffffffu, s,   jj & 31);
                float w0 = __shfl_sync(0xffffffffu, aw0, jj & 31);
                float w1 = __shfl_sync(0xffffffffu, aw1, jj & 31);
                float ww = isH1 ? w1 : w0;
                if (jj >= cnt) ww = 0.f;
                uint4 raw = hv[(size_t)sj * 16 + g];
                float2 f0 = __half22float2(*reinterpret_cast<__half2*>(&raw.x));
                float2 f1 = __half22float2(*reinterpret_cast<__half2*>(&raw.y));
                float2 f2 = __half22float2(*reinterpret_cast<__half2*>(&raw.z));
                float2 f3 = __half22float2(*reinterpret_cast<__half2*>(&raw.w));
                acc[0] = fmaf(ww, f0.x, acc[0]);
                acc[1] = fmaf(ww, f0.y, acc[1]);
                acc[2] = fmaf(ww, f1.x, acc[2]);
                acc[3] = fmaf(ww, f1.y, acc[3]);
                acc[4] = fmaf(ww, f2.x, acc[4]);
                acc[5] = fmaf(ww, f2.y, acc[5]);
                acc[6] = fmaf(ww, f3.x, acc[6]);
                acc[7] = fmaf(ww, f3.y, acc[7]);
            }
        }
    }

    // edge-pair reduce (xor 16); lanes 0-15 hold the 128 channels head-separated
#pragma unroll
    for (int i = 0; i < 8; i++)
        acc[i] += __shfl_xor_sync(0xffffffffu, acc[i], 16);

    if (active && lane < 16) {
        float* dst = g_tmp + (size_t)d * HC + g * 8;
        *reinterpret_cast<float4*>(dst)     = make_float4(acc[0], acc[1], acc[2], acc[3]);
        *reinterpret_cast<float4*>(dst + 4) = make_float4(acc[4], acc[5], acc[6], acc[7]);
    }

    // block-reduce exp sums -> 2 atomics per block
#pragma unroll
    for (int o = 16; o > 0; o >>= 1) {
        ws0 += __shfl_xor_sync(0xffffffffu, ws0, o);
        ws1 += __shfl_xor_sync(0xffffffffu, ws1, o);
    }
    __shared__ float sm0[8], sm1[8];
    if (lane == 0) { sm0[wIdx] = ws0; sm1[wIdx] = ws1; }
    __syncthreads();
    if (threadIdx.x == 0) {
        float t0 = 0.f, t1 = 0.f;
#pragma unroll
        for (int i = 0; i < 8; i++) { t0 += sm0[i]; t1 += sm1[i]; }
        atomicAdd(&g_sum[layer * 2],     t0);
        atomicAdd(&g_sum[layer * 2 + 1], t1);
    }
}

// ---------------- finalize: out = tmp0*inv0 + tmp1*inv1 + b2 -----------------
__global__ void __launch_bounds__(256) finalize_kernel(
    int N, float* __restrict__ out, const float* __restrict__ bias)
{
    int i = blockIdx.x * blockDim.x + threadIdx.x;
    if (i >= N * 16) return;
    int d = i >> 4, q = i & 15;
    float inv0 = 0.5f * HSCALE_INV / (g_sum[2] + 1e-10f);
    float inv1 = 0.5f * HSCALE_INV / (g_sum[3] + 1e-10f);
    const float4* t4 = reinterpret_cast<const float4*>(g_tmp) + (size_t)d * 32;
    float4 t0 = t4[q], t1 = t4[q + 16];
    float4 b  = reinterpret_cast<const float4*>(bias)[q];
    float4 o;
    o.x = fmaf(t0.x, inv0, fmaf(t1.x, inv1, b.x));
    o.y = fmaf(t0.y, inv0, fmaf(t1.y, inv1, b.y));
    o.z = fmaf(t0.z, inv0, fmaf(t1.z, inv1, b.z));
    o.w = fmaf(t0.w, inv0, fmaf(t1.w, inv1, b.w));
    reinterpret_cast<float4*>(out)[i] = o;
}

// ---------------- launch ----------------
extern "C" void kernel_launch(void* const* d_in, const int* in_sizes, int n_in,
                              void* d_out, int out_size)
{
    const float* x    = (const float*)d_in[0];
    const int*   ei32 = (const int*)d_in[1];
    const float* W1   = (const float*)d_in[2];
    const float* att1 = (const float*)d_in[3];
    const float* b1   = (const float*)d_in[4];
    const float* W2   = (const float*)d_in[5];
    const float* att2 = (const float*)d_in[6];
    const float* b2   = (const float*)d_in[7];
    float* out = (float*)d_out;

    int N  = in_sizes[0] / FIN;
    int E  = in_sizes[1] / 2;
    int ET = E + N;
    int nb = (N + SCAN_CHUNK - 1) / SCAN_CHUNK;

    int gemmBlocks = (N + 127) / 128;
    int histBlocks = (E + 255) / 256;

    // 1: GEMM1 + degree histogram fused
    gemm_tc_kernel<FIN><<<gemmBlocks + histBlocks, 256>>>(
        x, 0, nullptr, W1, att1, N, ei32, E, gemmBlocks);
    partial_kernel<<<nb, 256>>>(N);                                     // 2
    offsets_kernel<<<nb, 256>>>(N, nb);                                 // 3
    scatter_kernel<<<(ET + 1023) / 1024, 256>>>(ei32, E, N);            // 4
    gather_kernel<<<(N * 32 + 255) / 256, 256>>>(N, 0);                 // 5
    // 6: GEMM2 with fused layer-1 normalization + bias + relu in the loader
    gemm_tc_kernel<CD><<<gemmBlocks, 256>>>(
        x, 1, b1, W2, att2, N, ei32, 0, gemmBlocks);
    gather_kernel<<<(N * 32 + 255) / 256, 256>>>(N, 1);                 // 7
    finalize_kernel<<<(N * 16 + 255) / 256, 256>>>(N, out, b2);         // 8
}

// round 13
// speedup vs baseline: 1.0095x; 1.0095x over previous
#include <cuda_runtime.h>
#include <cuda_fp16.h>
#include <math.h>

// Problem constants (shapes fixed by the dataset)
#define HC   128      // HEADS * C
#define CD   64       // C
#define FIN  128      // Fin of layer 1
#define NMAX 50048
#define EMAX 800256
#define ETMAX (NMAX + EMAX)
#define SCAN_CHUNK 2048   // elements per scan block (256 thr x 8)
#define HSCALE 4096.0f    // fp16 storage scale (keeps layer-2 h out of subnormals)
#define HSCALE_INV (1.0f / 4096.0f)

// ---------------- scratch (device globals; no allocation) ----------------
__device__ __align__(16) __half g_hh[(size_t)NMAX * HC];    // GEMM output * HSCALE, fp16
__device__ __align__(16) float  g_tmp[(size_t)NMAX * HC];   // raw gather acc [N,2,64] fp32
__device__ __align__(8)  float  g_sdst[NMAX * 2];           // per-node dst-scores [N,H]
__device__ __align__(8)  float  g_ssrc[NMAX * 2];           // per-node src-scores [N,H]
__device__ float    g_sum[4];                   // per-layer per-head exp sums
// CSR: g_deg stores EXTRA in-degree (self-loop excluded); zero-init and
// reset-after-use by offsets_kernel -> replay-clean with no init pass.
__device__ __align__(16) int g_deg[NMAX];
__device__ __align__(16) int g_roff[NMAX + 8];
__device__ int      g_rank[EMAX];               // per-edge rank among same-dst edges
__device__ int      g_csr[ETMAX];               // src per incoming edge (dst-sorted)
__device__ int      g_bsum[256];                // per-block degree sums

__device__ __forceinline__ unsigned f2tf32(float f) {
    unsigned r;
    asm("cvt.rna.tf32.f32 %0, %1;" : "=r"(r) : "f"(f));
    return r;
}

__device__ __forceinline__ void mma_tf32(
    float& c0, float& c1, float& c2, float& c3,
    unsigned a0, unsigned a1, unsigned a2, unsigned a3,
    unsigned b0, unsigned b1)
{
    asm volatile(
        "mma.sync.aligned.m16n8k8.row.col.f32.tf32.tf32.f32 "
        "{%0,%1,%2,%3}, {%4,%5,%6,%7}, {%8,%9}, {%0,%1,%2,%3};"
        : "+f"(c0), "+f"(c1), "+f"(c2), "+f"(c3)
        : "r"(a0), "r"(a1), "r"(a2), "r"(a3), "r"(b0), "r"(b1));
}

// per-block dtype detection: int64 edges (<2^31) have all-zero odd words.
__device__ __forceinline__ int block_detect_is32(const int* __restrict__ ei32) {
    __shared__ int sIs32;
    if (threadIdx.x == 0) {
        unsigned v = 0;
#pragma unroll
        for (int i = 0; i < 32; i++) v |= (unsigned)ei32[2 * i + 1];
        sIs32 = (v != 0u) ? 1 : 0;
    }
    __syncthreads();
    return sIs32;
}

__device__ __forceinline__ void load_edge(const int* __restrict__ ei32,
                                          int e, int E, int is32, int& s, int& d) {
    if (is32) { s = ei32[e];     d = ei32[E + e]; }
    else      { s = ei32[2 * e]; d = ei32[2 * (E + e)]; }
}

__device__ __forceinline__ float lrexp(float a) {
    a = (a >= 0.f) ? a : 0.2f * a;
    return __expf(a);
}

// ---------------- tf32 tensor-core GEMM + fused score epilogue --------------
// Blocks [0, nGemm): GEMM. Blocks >= nGemm: degree histogram + per-edge rank
// (layer 1 only). fromTmp=1 (layer 2): loader reads g_tmp and applies layer-1
// normalization (inv from g_sum[0,1]) + bias + relu on the fly.
#define TP 36   // smem pitch (32 k + 4 pad) -> conflict-free fragment loads

template <int K>
__global__ void __launch_bounds__(256) gemm_tc_kernel(
    const float* __restrict__ X0, int fromTmp, const float* __restrict__ bias1,
    const float* __restrict__ W, const float* __restrict__ att, int N,
    const int* __restrict__ ei32, int nHistE, int nGemm)
{
    // ---- histogram part (layer-1 launch only) ----
    if (blockIdx.x >= (unsigned)nGemm) {
        int hb = blockIdx.x - nGemm;
        int is32 = block_detect_is32(ei32);
        if (hb == 0 && threadIdx.x < 4) g_sum[threadIdx.x] = 0.f;
        int e = hb * 256 + threadIdx.x;
        if (e < nHistE) {
            int s, d;
            load_edge(ei32, e, nHistE, is32, s, d);
            g_rank[e] = atomicAdd(&g_deg[d], 1);   // rank among same-dst edges
        }
        return;
    }

    __shared__ __align__(16) unsigned sX[128 * TP];
    __shared__ __align__(16) unsigned sW[128 * TP];
    __shared__ float sAtt[256];

    int t    = threadIdx.x;
    int wid  = t >> 5;
    int lane = t & 31;
    int gid  = lane >> 2;
    int tid  = lane & 3;
    int wm   = wid & 3;
    int wn   = wid >> 2;    // head
    int row0 = blockIdx.x * 128;
    int wrow = wm * 32;
    int wcol = wn * 64;

    if (t < 256) sAtt[t] = att[t];

    float inv0 = 0.f, inv1 = 0.f;
    if (fromTmp) {
        inv0 = 0.5f * HSCALE_INV / (g_sum[0] + 1e-10f);
        inv1 = 0.5f * HSCALE_INV / (g_sum[1] + 1e-10f);
    }

    float c[2][8][4];
#pragma unroll
    for (int mt = 0; mt < 2; mt++)
#pragma unroll
        for (int nt = 0; nt < 8; nt++)
#pragma unroll
            for (int i = 0; i < 4; i++) c[mt][nt][i] = 0.f;

    for (int kc = 0; kc < K; kc += 32) {
#pragma unroll
        for (int it = 0; it < 4; it++) {
            int idx = t + it * 256;
            int r = idx >> 3;
            int q = idx & 7;
            int k = q * 4;

            float4 v = make_float4(0.f, 0.f, 0.f, 0.f);
            int grow = row0 + r;
            if (grow < N) {
                if (fromTmp) {
                    // layer-1 output = relu(tmp0*inv0 + tmp1*inv1 + b1)
                    int qi = (kc + k) >> 2;   // float4 index in [0,16)
                    const float4* t4 = reinterpret_cast<const float4*>(g_tmp)
                                       + (size_t)grow * 32;
                    float4 t0 = t4[qi], t1 = t4[qi + 16];
                    float4 bb = reinterpret_cast<const float4*>(bias1)[qi];
                    v.x = fmaxf(fmaf(t0.x, inv0, fmaf(t1.x, inv1, bb.x)), 0.f);
                    v.y = fmaxf(fmaf(t0.y, inv0, fmaf(t1.y, inv1, bb.y)), 0.f);
                    v.z = fmaxf(fmaf(t0.z, inv0, fmaf(t1.z, inv1, bb.z)), 0.f);
                    v.w = fmaxf(fmaf(t0.w, inv0, fmaf(t1.w, inv1, bb.w)), 0.f);
                } else {
                    v = *reinterpret_cast<const float4*>(X0 + (size_t)grow * K + kc + k);
                }
            }
            uint4 tv = make_uint4(f2tf32(v.x), f2tf32(v.y), f2tf32(v.z), f2tf32(v.w));
            *reinterpret_cast<uint4*>(&sX[r * TP + k]) = tv;

            float4 w = *reinterpret_cast<const float4*>(W + (size_t)r * K + kc + k);
            uint4 tw = make_uint4(f2tf32(w.x), f2tf32(w.y), f2tf32(w.z), f2tf32(w.w));
            *reinterpret_cast<uint4*>(&sW[r * TP + k]) = tw;
        }
        __syncthreads();

#pragma unroll
        for (int ks = 0; ks < 4; ks++) {
            int k0 = ks * 8;
            unsigned a[2][4];
#pragma unroll
            for (int mt = 0; mt < 2; mt++) {
                int r = wrow + mt * 16 + gid;
                a[mt][0] = sX[r * TP + k0 + tid];
                a[mt][1] = sX[(r + 8) * TP + k0 + tid];
                a[mt][2] = sX[r * TP + k0 + tid + 4];
                a[mt][3] = sX[(r + 8) * TP + k0 + tid + 4];
            }
            unsigned b[8][2];
#pragma unroll
            for (int nt = 0; nt < 8; nt++) {
                int n = wcol + nt * 8 + gid;
                b[nt][0] = sW[n * TP + k0 + tid];
                b[nt][1] = sW[n * TP + k0 + tid + 4];
            }
#pragma unroll
            for (int mt = 0; mt < 2; mt++)
#pragma unroll
                for (int nt = 0; nt < 8; nt++)
                    mma_tf32(c[mt][nt][0], c[mt][nt][1], c[mt][nt][2], c[mt][nt][3],
                             a[mt][0], a[mt][1], a[mt][2], a[mt][3],
                             b[nt][0], b[nt][1]);
        }
        __syncthreads();
    }

    float dp[2][2] = {{0.f, 0.f}, {0.f, 0.f}};
    float sp[2][2] = {{0.f, 0.f}, {0.f, 0.f}};

#pragma unroll
    for (int mt = 0; mt < 2; mt++) {
        int rlo = row0 + wrow + mt * 16 + gid;
        int rhi = rlo + 8;
#pragma unroll
        for (int nt = 0; nt < 8; nt++) {
            int cw = nt * 8 + tid * 2;
            int gc = wcol + cw;
            float c0 = c[mt][nt][0], c1 = c[mt][nt][1];
            float c2 = c[mt][nt][2], c3 = c[mt][nt][3];
            if (rlo < N)
                *reinterpret_cast<__half2*>(g_hh + (size_t)rlo * HC + gc) =
                    __floats2half2_rn(c0 * HSCALE, c1 * HSCALE);
            if (rhi < N)
                *reinterpret_cast<__half2*>(g_hh + (size_t)rhi * HC + gc) =
                    __floats2half2_rn(c2 * HSCALE, c3 * HSCALE);

            float ad0 = sAtt[wn * 128 + cw],      ad1 = sAtt[wn * 128 + cw + 1];
            float as0 = sAtt[wn * 128 + 64 + cw], as1 = sAtt[wn * 128 + 64 + cw + 1];
            dp[mt][0] = fmaf(c0, ad0, fmaf(c1, ad1, dp[mt][0]));
            sp[mt][0] = fmaf(c0, as0, fmaf(c1, as1, sp[mt][0]));
            dp[mt][1] = fmaf(c2, ad0, fmaf(c3, ad1, dp[mt][1]));
            sp[mt][1] = fmaf(c2, as0, fmaf(c3, as1, sp[mt][1]));
        }
    }
#pragma unroll
    for (int mt = 0; mt < 2; mt++)
#pragma unroll
        for (int u = 0; u < 2; u++) {
#pragma unroll
            for (int o = 1; o <= 2; o <<= 1) {
                dp[mt][u] += __shfl_xor_sync(0xffffffffu, dp[mt][u], o);
                sp[mt][u] += __shfl_xor_sync(0xffffffffu, sp[mt][u], o);
            }
            if (tid == 0) {
                int row = row0 + wrow + mt * 16 + gid + u * 8;
                if (row < N) {
                    g_sdst[row * 2 + wn] = dp[mt][u];
                    g_ssrc[row * 2 + wn] = sp[mt][u];
                }
            }
        }
}

// ---------------- scan phase 1: per-block sums (vectorized, warp reduce) ----
__global__ void __launch_bounds__(256) partial_kernel(int N) {
    int b = blockIdx.x, t = threadIdx.x;
    int beg = b * SCAN_CHUNK + t * 8;
    int s = 0;
    if (beg + 8 <= N) {
        int4 a = *reinterpret_cast<const int4*>(g_deg + beg);
        int4 c = *reinterpret_cast<const int4*>(g_deg + beg + 4);
        s = a.x + a.y + a.z + a.w + c.x + c.y + c.z + c.w + 8;
    } else {
#pragma unroll
        for (int i = 0; i < 8; i++) {
            int idx = beg + i;
            if (idx < N) s += g_deg[idx] + 1;
        }
    }
    s = __reduce_add_sync(0xffffffffu, s);
    __shared__ int wsum[8];
    if ((t & 31) == 0) wsum[t >> 5] = s;
    __syncthreads();
    if (t == 0) {
        int tot = 0;
#pragma unroll
        for (int i = 0; i < 8; i++) tot += wsum[i];
        g_bsum[b] = tot;
    }
}

// ---------------- scan phase 2: offsets (warp-shuffle scan, vectorized) -----
__global__ void __launch_bounds__(256) offsets_kernel(int N, int nb) {
    __shared__ int sBase;
    __shared__ int wsum[8];
    int b = blockIdx.x, t = threadIdx.x;
    int lane = t & 31, w = t >> 5;

    if (t < 32) {
        int val = (t < nb) ? g_bsum[t] : 0;
        int base = __reduce_add_sync(0xffffffffu, (t < b) ? val : 0);
        if (t == 0) sBase = base;
        if (b == 0) {
            int total = __reduce_add_sync(0xffffffffu, val);
            if (t == 0) g_roff[N] = total;
        }
    }

    int beg = b * SCAN_CHUNK + t * 8;
    int v[8];
    int s;
    bool vec = (beg + 8 <= N);
    if (vec) {
        int4 a = *reinterpret_cast<const int4*>(g_deg + beg);
        int4 c = *reinterpret_cast<const int4*>(g_deg + beg + 4);
        v[0] = a.x + 1; v[1] = a.y + 1; v[2] = a.z + 1; v[3] = a.w + 1;
        v[4] = c.x + 1; v[5] = c.y + 1; v[6] = c.z + 1; v[7] = c.w + 1;
        int4 z = make_int4(0, 0, 0, 0);
        *reinterpret_cast<int4*>(g_deg + beg)     = z;
        *reinterpret_cast<int4*>(g_deg + beg + 4) = z;
    } else {
#pragma unroll
        for (int i = 0; i < 8; i++) {
            int idx = beg + i;
            v[i] = (idx < N) ? (g_deg[idx] + 1) : 0;
            if (idx < N) g_deg[idx] = 0;
        }
    }
    s = v[0] + v[1] + v[2] + v[3] + v[4] + v[5] + v[6] + v[7];

    int ps = s;
#pragma unroll
    for (int o = 1; o < 32; o <<= 1) {
        int x = __shfl_up_sync(0xffffffffu, ps, o);
        if (lane >= o) ps += x;
    }
    if (lane == 31) wsum[w] = ps;
    __syncthreads();
    int wbase = 0;
#pragma unroll
    for (int j = 0; j < 8; j++) wbase += (j < w) ? wsum[j] : 0;

    int excl = (ps - s) + wbase + sBase;
    int r[8];
#pragma unroll
    for (int i = 0; i < 8; i++) { r[i] = excl; excl += v[i]; }
    if (vec) {
        *reinterpret_cast<int4*>(g_roff + beg)     = make_int4(r[0], r[1], r[2], r[3]);
        *reinterpret_cast<int4*>(g_roff + beg + 4) = make_int4(r[4], r[5], r[6], r[7]);
    } else {
#pragma unroll
        for (int i = 0; i < 8; i++) {
            int idx = beg + i;
            if (idx < N) g_roff[idx] = r[i];
        }
    }
}

// ---------------- scatter: atomic-free CSR build via precomputed ranks -------
// slot roff[d] = self loop; edges at roff[d] + 1 + rank[e].
__global__ void __launch_bounds__(256) scatter_kernel(
    const int* __restrict__ ei32, int E, int N)
{
    int is32 = block_detect_is32(ei32);
    int e = blockIdx.x * blockDim.x + threadIdx.x;
    int ET = E + N;
    if (e >= ET) return;
    int pos, s;
    if (e < E) {
        int d;
        load_edge(ei32, e, E, is32, s, d);
        pos = g_roff[d] + 1 + g_rank[e];
    } else {
        s = e - E;
        pos = g_roff[s];
    }
    g_csr[pos] = s;
}

// ---------------- gather: raw (unnormalized) acc + fused denominator sums ----
__global__ void __launch_bounds__(256) gather_kernel(int N, int layer)
{
    int wid  = (blockIdx.x * blockDim.x + threadIdx.x) >> 5;
    int lane = threadIdx.x & 31;
    int wIdx = threadIdx.x >> 5;
    bool active = (wid < N);
    int d = active ? wid : 0;

    int g   = lane & 15;
    int sub = lane >> 4;
    bool isH1 = (g >= 8);

    const uint4* hv = reinterpret_cast<const uint4*>(g_hh);
    float acc[8];
#pragma unroll
    for (int i = 0; i < 8; i++) acc[i] = 0.f;
    float ws0 = 0.f, ws1 = 0.f;

    if (active) {
        int beg = g_roff[d];
        int end = g_roff[d + 1];
        float2 scd = *reinterpret_cast<const float2*>(g_sdst + d * 2);

        for (int base = beg; base < end; base += 32) {
            int idx = base + lane;
            int   s   = 0;
            float aw0 = 0.f, aw1 = 0.f;
            if (idx < end) {
                s = g_csr[idx];
                float2 scs = *reinterpret_cast<const float2*>(g_ssrc + s * 2);
                aw0 = lrexp(scd.x + scs.x);
                aw1 = lrexp(scd.y + scs.y);
                ws0 += aw0;
                ws1 += aw1;
            }
            int cnt = min(32, end - base);
#pragma unroll 4
            for (int j = 0; j < cnt; j += 2) {
                int jj = j + sub;
                int   sj = __shfl_sync(0xffffffffu, s,   jj & 31);
                float w0 = __shfl_sync(0xffffffffu, aw0, jj & 31);
                float w1 = __shfl_sync(0xffffffffu, aw1, jj & 31);
                float ww = isH1 ? w1 : w0;
                if (jj >= cnt) ww = 0.f;
                uint4 raw = hv[(size_t)sj * 16 + g];
                float2 f0 = __half22float2(*reinterpret_cast<__half2*>(&raw.x));
                float2 f1 = __half22float2(*reinterpret_cast<__half2*>(&raw.y));
                float2 f2 = __half22float2(*reinterpret_cast<__half2*>(&raw.z));
                float2 f3 = __half22float2(*reinterpret_cast<__half2*>(&raw.w));
                acc[0] = fmaf(ww, f0.x, acc[0]);
                acc[1] = fmaf(ww, f0.y, acc[1]);
                acc[2] = fmaf(ww, f1.x, acc[2]);
                acc[3] = fmaf(ww, f1.y, acc[3]);
                acc[4] = fmaf(ww, f2.x, acc[4]);
                acc[5] = fmaf(ww, f2.y, acc[5]);
                acc[6] = fmaf(ww, f3.x, acc[6]);
                acc[7] = fmaf(ww, f3.y, acc[7]);
            }
        }
    }

    // edge-pair reduce (xor 16); lanes 0-15 hold the 128 channels head-separated
#pragma unroll
    for (int i = 0; i < 8; i++)
        acc[i] += __shfl_xor_sync(0xffffffffu, acc[i], 16);

    if (active && lane < 16) {
        float* dst = g_tmp + (size_t)d * HC + g * 8;
        *reinterpret_cast<float4*>(dst)     = make_float4(acc[0], acc[1], acc[2], acc[3]);
        *reinterpret_cast<float4*>(dst + 4) = make_float4(acc[4], acc[5], acc[6], acc[7]);
    }

    // block-reduce exp sums -> 2 atomics per block
#pragma unroll
    for (int o = 16; o > 0; o >>= 1) {
        ws0 += __shfl_xor_sync(0xffffffffu, ws0, o);
        ws1 += __shfl_xor_sync(0xffffffffu, ws1, o);
    }
    __shared__ float sm0[8], sm1[8];
    if (lane == 0) { sm0[wIdx] = ws0; sm1[wIdx] = ws1; }
    __syncthreads();
    if (threadIdx.x == 0) {
        float t0 = 0.f, t1 = 0.f;
#pragma unroll
        for (int i = 0; i < 8; i++) { t0 += sm0[i]; t1 += sm1[i]; }
        atomicAdd(&g_sum[layer * 2],     t0);
        atomicAdd(&g_sum[layer * 2 + 1], t1);
    }
}

// ---------------- finalize: out = tmp0*inv0 + tmp1*inv1 + b2 -----------------
__global__ void __launch_bounds__(256) finalize_kernel(
    int N, float* __restrict__ out, const float* __restrict__ bias)
{
    int i = blockIdx.x * blockDim.x + threadIdx.x;
    if (i >= N * 16) return;
    int d = i >> 4, q = i & 15;
    float inv0 = 0.5f * HSCALE_INV / (g_sum[2] + 1e-10f);
    float inv1 = 0.5f * HSCALE_INV / (g_sum[3] + 1e-10f);
    const float4* t4 = reinterpret_cast<const float4*>(g_tmp) + (size_t)d * 32;
    float4 t0 = t4[q], t1 = t4[q + 16];
    float4 b  = reinterpret_cast<const float4*>(bias)[q];
    float4 o;
    o.x = fmaf(t0.x, inv0, fmaf(t1.x, inv1, b.x));
    o.y = fmaf(t0.y, inv0, fmaf(t1.y, inv1, b.y));
    o.z = fmaf(t0.z, inv0, fmaf(t1.z, inv1, b.z));
    o.w = fmaf(t0.w, inv0, fmaf(t1.w, inv1, b.w));
    reinterpret_cast<float4*>(out)[i] = o;
}

// ---------------- launch ----------------
extern "C" void kernel_launch(void* const* d_in, const int* in_sizes, int n_in,
                              void* d_out, int out_size)
{
    const float* x    = (const float*)d_in[0];
    const int*   ei32 = (const int*)d_in[1];
    const float* W1   = (const float*)d_in[2];
    const float* att1 = (const float*)d_in[3];
    const float* b1   = (const float*)d_in[4];
    const float* W2   = (const float*)d_in[5];
    const float* att2 = (const float*)d_in[6];
    const float* b2   = (const float*)d_in[7];
    float* out = (float*)d_out;

    int N  = in_sizes[0] / FIN;
    int E  = in_sizes[1] / 2;
    int ET = E + N;
    int nb = (N + SCAN_CHUNK - 1) / SCAN_CHUNK;

    int gemmBlocks = (N + 127) / 128;
    int histBlocks = (E + 255) / 256;

    // 1: GEMM1 + degree histogram (with per-edge rank capture) fused
    gemm_tc_kernel<FIN><<<gemmBlocks + histBlocks, 256>>>(
        x, 0, nullptr, W1, att1, N, ei32, E, gemmBlocks);
    partial_kernel<<<nb, 256>>>(N);                                     // 2
    offsets_kernel<<<nb, 256>>>(N, nb);                                 // 3
    scatter_kernel<<<(ET + 255) / 256, 256>>>(ei32, E, N);              // 4 (atomic-free)
    gather_kernel<<<(N * 32 + 255) / 256, 256>>>(N, 0);                 // 5
    // 6: GEMM2 with fused layer-1 normalization + bias + relu in the loader
    gemm_tc_kernel<CD><<<gemmBlocks, 256>>>(
        x, 1, b1, W2, att2, N, ei32, 0, gemmBlocks);
    gather_kernel<<<(N * 32 + 255) / 256, 256>>>(N, 1);                 // 7
    finalize_kernel<<<(N * 16 + 255) / 256, 256>>>(N, out, b2);         // 8
}